// round 9
// baseline (speedup 1.0000x reference)
#include <cuda_runtime.h>
#include <cstdint>
#include <cstddef>

#define CH 64
#define ENT_MAX 100000
#define GR 512          // rows per gemm block

__device__ int g_counts[ENT_MAX];

// is64 detection from edge_type[0] (values in [2,18); an 8B read of an int32
// buffer is >= 2^32, never in [2,64)).
__device__ __forceinline__ bool detect64(const void* et) {
    long long v = ((const long long*)et)[0];
    return (v >= 2 && v < 64);
}

// ---------------------------------------------------------------------------
// KG aggregate, single pass: 16 threads/edge (half-warp), thread s handles
// float4 slice s of the 64-channel row. Indices loaded ONCE per half-warp by
// the lead lane and shfl-broadcast (16x less index LSU traffic than r1).
// Gather entity_emb[tail]*weight[rel] -> red.global.add.v4.f32 into
// ent_out[head]; lead lane REDs the count.
// ---------------------------------------------------------------------------
__global__ void __launch_bounds__(256) edge_red_kernel(
    const void* __restrict__ ei, const void* __restrict__ et,
    const float* __restrict__ entity_emb, const float* __restrict__ weight,
    float* __restrict__ ent_out, int E)
{
    int t = blockIdx.x * 256 + threadIdx.x;
    int e = t >> 4;
    if (e >= E) return;
    int lane = threadIdx.x & 31;
    int s = lane & 15;

    int head = 0, tail = 0, rel = 0;
    if (s == 0) {
        if (detect64(et)) {
            const long long* p = (const long long*)ei;
            head = (int)p[e];
            tail = (int)p[(size_t)E + e];
            rel  = (int)((const long long*)et)[e] - 2;
        } else {
            const int* p = (const int*)ei;
            head = p[e];
            tail = p[(size_t)E + e];
            rel  = ((const int*)et)[e] - 2;
        }
    }
    int src = lane & 16;                       // 0 for lanes 0-15, 16 for 16-31
    head = __shfl_sync(0xffffffffu, head, src);
    tail = __shfl_sync(0xffffffffu, tail, src);
    rel  = __shfl_sync(0xffffffffu, rel,  src);

    float4 a = ((const float4*)(entity_emb + (size_t)tail * CH))[s];
    float4 w = ((const float4*)(weight + (size_t)rel * CH))[s];
    float4 v = make_float4(a.x * w.x, a.y * w.y, a.z * w.z, a.w * w.w);

    float* dst = ent_out + (size_t)head * CH + s * 4;
    asm volatile("red.global.add.v4.f32 [%0], {%1,%2,%3,%4};"
                 :: "l"(dst), "f"(v.x), "f"(v.y), "f"(v.z), "f"(v.w)
                 : "memory");

    if (s == 0)
        asm volatile("red.global.add.s32 [%0], 1;"
                     :: "l"(&g_counts[head]) : "memory");
}

// ---------------------------------------------------------------------------
// Divide each entity row by max(count, 1). One thread per float4.
// ---------------------------------------------------------------------------
__global__ void __launch_bounds__(256) finalize_kernel(
    float* __restrict__ ent_out, int n_ent)
{
    int i = blockIdx.x * 256 + threadIdx.x;   // float4 index
    int total = n_ent * (CH / 4);
    if (i >= total) return;
    int ent = i >> 4;
    float inv = 1.0f / (float)max(g_counts[ent], 1);
    float4 v = ((const float4*)ent_out)[i];
    v.x *= inv; v.y *= inv; v.z *= inv; v.w *= inv;
    ((float4*)ent_out)[i] = v;
}

// ---------------------------------------------------------------------------
// Fused GEMMs: out = 2*(mat @ A) (softmax row-sum == 1 collapses the score
// term to a factor of 2). 512 rows/block, 512 threads; thread (g,q) computes
// rows {g+64i} x cols [8q,8q+8) with packed fma.rn.f32x2.
// ---------------------------------------------------------------------------
__global__ void __launch_bounds__(512, 1) gemm_fused_kernel(
    const float* __restrict__ ia, int n_items,
    const float* __restrict__ ua, int n_users,
    const float* __restrict__ A,
    float* __restrict__ item_out, float* __restrict__ user_out,
    int item_blocks)
{
    extern __shared__ float sm[];
    float*  sA  = sm;                       // 64x64, permuted
    float4* sM4 = (float4*)(sm + 4096);     // 512 rows x 17 float4

    const float* mat; float* out; int nrows; int row0;
    if ((int)blockIdx.x < item_blocks) {
        mat = ia; out = item_out; nrows = n_items; row0 = blockIdx.x * GR;
    } else {
        mat = ua; out = user_out; nrows = n_users;
        row0 = (blockIdx.x - item_blocks) * GR;
    }

    int tid = threadIdx.x;

    const float4* A4 = (const float4*)A;
    float4* sA4 = (float4*)sA;
    for (int idx = tid; idx < 1024; idx += 512) {
        int k = idx >> 4, c = idx & 15;
        sA4[k * 16 + ((c & 1) << 3) + (c >> 1)] = A4[idx];
    }
    const float4* mat4 = (const float4*)mat;
    for (int idx = tid; idx < GR * 16; idx += 512) {
        int r = idx >> 4, c = idx & 15;
        int gr = row0 + r;
        float4 v = make_float4(0.f, 0.f, 0.f, 0.f);
        if (gr < nrows) v = mat4[(size_t)gr * 16 + c];
        sM4[r * 17 + c] = v;
    }
    __syncthreads();

    int g = tid >> 3, q = tid & 7;
    unsigned long long acc[8][4];
    #pragma unroll
    for (int i = 0; i < 8; i++)
        #pragma unroll
        for (int p = 0; p < 4; p++) acc[i][p] = 0ull;

    const ulonglong2* sA8 = (const ulonglong2*)sA;

    for (int kk = 0; kk < 16; kk++) {
        float4 mv[8];
        #pragma unroll
        for (int i = 0; i < 8; i++) mv[i] = sM4[(g + 64 * i) * 17 + kk];

        #pragma unroll
        for (int u = 0; u < 4; u++) {
            int k = kk * 4 + u;
            ulonglong2 b0 = sA8[k * 16 + q];
            ulonglong2 b1 = sA8[k * 16 + 8 + q];
            #pragma unroll
            for (int i = 0; i < 8; i++) {
                float mu = (u == 0) ? mv[i].x : (u == 1) ? mv[i].y
                         : (u == 2) ? mv[i].z : mv[i].w;
                unsigned long long m2;
                asm("mov.b64 %0, {%1, %1};" : "=l"(m2) : "f"(mu));
                asm("fma.rn.f32x2 %0, %1, %2, %0;" : "+l"(acc[i][0]) : "l"(b0.x), "l"(m2));
                asm("fma.rn.f32x2 %0, %1, %2, %0;" : "+l"(acc[i][1]) : "l"(b0.y), "l"(m2));
                asm("fma.rn.f32x2 %0, %1, %2, %0;" : "+l"(acc[i][2]) : "l"(b1.x), "l"(m2));
                asm("fma.rn.f32x2 %0, %1, %2, %0;" : "+l"(acc[i][3]) : "l"(b1.y), "l"(m2));
            }
        }
    }

    #pragma unroll
    for (int i = 0; i < 8; i++) {
        int gr = row0 + g + 64 * i;
        if (gr < nrows) {
            ulonglong2* o = (ulonglong2*)(out + (size_t)gr * CH + q * 8);
            unsigned long long d0, d1, d2, d3;
            asm("add.rn.f32x2 %0, %1, %1;" : "=l"(d0) : "l"(acc[i][0]));
            asm("add.rn.f32x2 %0, %1, %1;" : "=l"(d1) : "l"(acc[i][1]));
            asm("add.rn.f32x2 %0, %1, %1;" : "=l"(d2) : "l"(acc[i][2]));
            asm("add.rn.f32x2 %0, %1, %1;" : "=l"(d3) : "l"(acc[i][3]));
            ulonglong2 w0; w0.x = d0; w0.y = d1;
            ulonglong2 w1; w1.x = d2; w1.y = d3;
            o[0] = w0; o[1] = w1;
        }
    }
}

// ---------------------------------------------------------------------------
// Launch: short edge chain (memset -> edge_red -> finalize) on the capture
// stream; independent GEMM forked onto a side stream (capture-legal event
// fork/join; streams/events are host objects, no device allocation).
// ---------------------------------------------------------------------------
extern "C" void kernel_launch(void* const* d_in, const int* in_sizes, int n_in,
                              void* d_out, int out_size)
{
    const float* entity_emb = (const float*)d_in[0];
    const float* aspect_emb = (const float*)d_in[3];
    const void*  edge_index = d_in[4];
    const void*  edge_type  = d_in[5];
    const float* ua_mat     = (const float*)d_in[6];
    const float* ia_mat     = (const float*)d_in[7];
    const float* weight     = (const float*)d_in[8];

    int n_ent   = in_sizes[0] / CH;
    int n_users = in_sizes[6] / CH;
    int n_items = in_sizes[7] / CH;
    int E       = in_sizes[5];

    float* out      = (float*)d_out;
    float* item_out = out;
    float* ent_out  = out + (size_t)n_items * CH;
    float* user_out = ent_out + (size_t)n_ent * CH;

    // --- fork side stream for the independent GEMM branch ---
    cudaStream_t s2 = 0;
    cudaEvent_t evFork = 0, evJoin = 0;
    bool forked = (cudaStreamCreateWithFlags(&s2, cudaStreamNonBlocking) == cudaSuccess)
               && (cudaEventCreateWithFlags(&evFork, cudaEventDisableTiming) == cudaSuccess)
               && (cudaEventCreateWithFlags(&evJoin, cudaEventDisableTiming) == cudaSuccess);
    if (forked) {
        cudaEventRecord(evFork, 0);
        cudaStreamWaitEvent(s2, evFork, 0);
    }

    // --- GEMM branch ---
    {
        int item_blocks = (n_items + GR - 1) / GR;
        int user_blocks = (n_users + GR - 1) / GR;
        int smem_bytes  = (4096 + GR * 68) * sizeof(float);   // 152 KB
        cudaFuncSetAttribute(gemm_fused_kernel,
                             cudaFuncAttributeMaxDynamicSharedMemorySize,
                             smem_bytes);
        gemm_fused_kernel<<<item_blocks + user_blocks, 512, smem_bytes,
                            forked ? s2 : 0>>>(
            ia_mat, n_items, ua_mat, n_users, aspect_emb,
            item_out, user_out, item_blocks);
    }

    // --- edge chain (default stream) ---
    void* counts_ptr = nullptr;
    cudaGetSymbolAddress(&counts_ptr, g_counts);
    cudaMemsetAsync(ent_out, 0, (size_t)n_ent * CH * sizeof(float));
    cudaMemsetAsync(counts_ptr, 0, (size_t)n_ent * sizeof(int));

    int eblocks = (int)(((long long)E * 16 + 255) / 256);
    edge_red_kernel<<<eblocks, 256>>>(edge_index, edge_type, entity_emb,
                                      weight, ent_out, E);

    finalize_kernel<<<(n_ent * (CH / 4) + 255) / 256, 256>>>(ent_out, n_ent);

    // --- join ---
    if (forked) {
        cudaEventRecord(evJoin, s2);
        cudaStreamWaitEvent(0, evJoin, 0);
        cudaStreamDestroy(s2);
        cudaEventDestroy(evFork);
        cudaEventDestroy(evJoin);
    }
}

// round 12
// speedup vs baseline: 1.1581x; 1.1581x over previous
#include <cuda_runtime.h>
#include <cstdint>
#include <cstddef>

#define CH 64
#define ENT_MAX 100000
#define E_MAX   1250000
#define GR 512            // rows per gemm block
#define STILE 1024        // scan tile

__device__ int g_hist[ENT_MAX];          // per-head edge count
__device__ int g_off[ENT_MAX];           // exclusive CSR offsets
__device__ int g_cur[ENT_MAX];           // scatter cursors
__device__ int g_packed[E_MAX];          // tail | rel<<20, grouped by head
__device__ long long g_desc[128];        // scan tile descriptors

// is64 detection from edge_type[0] (values in [2,18); an 8B read of an int32
// buffer is >= 2^32, never in [2,64)).
__device__ __forceinline__ bool detect64(const void* et) {
    long long v = ((const long long*)et)[0];
    return (v >= 2 && v < 64);
}

// ---------------------------------------------------------------------------
// 1) histogram of heads, 4 edges/thread, vector loads. Block 0 also zeroes
// the scan descriptors (read only by the NEXT launch -> no ordering needed).
// ---------------------------------------------------------------------------
__global__ void __launch_bounds__(256) hist_kernel(
    const void* __restrict__ ei, const void* __restrict__ et, int E)
{
    if (blockIdx.x == 0 && threadIdx.x < 128) g_desc[threadIdx.x] = 0;

    int base = (blockIdx.x * 256 + threadIdx.x) * 4;
    if (base >= E) return;
    int h[4];
    int m = E - base; if (m > 4) m = 4;
    if (detect64(et)) {
        const longlong2* p = (const longlong2*)((const long long*)ei + base);
        if (m == 4) {
            longlong2 a = p[0], b = p[1];
            h[0] = (int)a.x; h[1] = (int)a.y; h[2] = (int)b.x; h[3] = (int)b.y;
        } else {
            for (int i = 0; i < m; i++) h[i] = (int)((const long long*)ei)[base + i];
        }
    } else {
        if (m == 4) {
            int4 a = *(const int4*)((const int*)ei + base);
            h[0] = a.x; h[1] = a.y; h[2] = a.z; h[3] = a.w;
        } else {
            for (int i = 0; i < m; i++) h[i] = ((const int*)ei)[base + i];
        }
    }
    for (int i = 0; i < m; i++) atomicAdd(&g_hist[h[i]], 1);
}

// ---------------------------------------------------------------------------
// 2) single-kernel exclusive scan of g_hist -> g_off, g_cur.
// Tile-local scan, publish (total<<32)|1, warp 0 lookback-sums earlier tiles
// (98 tiles <= 148 SMs, dispatched in bid order -> all resident, no deadlock).
// ---------------------------------------------------------------------------
__global__ void __launch_bounds__(STILE) scan_kernel(int n)
{
    __shared__ int wsum[32];
    __shared__ int sprefix;
    int tile = blockIdx.x, t = threadIdx.x, lane = t & 31, w = t >> 5;
    int i = tile * STILE + t;
    int v = (i < n) ? g_hist[i] : 0;
    int x = v;
    #pragma unroll
    for (int o = 1; o < 32; o <<= 1) {
        int y = __shfl_up_sync(~0u, x, o);
        if (lane >= o) x += y;
    }
    if (lane == 31) wsum[w] = x;
    __syncthreads();
    if (w == 0) {
        int y = wsum[lane];
        #pragma unroll
        for (int o = 1; o < 32; o <<= 1) {
            int z = __shfl_up_sync(~0u, y, o);
            if (lane >= o) y += z;
        }
        wsum[lane] = y;
    }
    __syncthreads();
    int incl  = x + (w ? wsum[w - 1] : 0);
    int total = wsum[31];
    if (t == 0) {
        __threadfence();
        ((volatile long long*)g_desc)[tile] = ((long long)total << 32) | 1ll;
    }
    if (w == 0) {
        int sum = 0;
        for (int base = 0; base < tile; base += 32) {
            int idx = base + lane;
            int a = 0;
            if (idx < tile) {
                long long d;
                do { d = ((volatile long long*)g_desc)[idx]; } while (d == 0);
                a = (int)(d >> 32);
            }
            #pragma unroll
            for (int o = 16; o >= 1; o >>= 1) a += __shfl_down_sync(~0u, a, o);
            if (lane == 0) sum += a;
        }
        if (lane == 0) sprefix = sum;
    }
    __syncthreads();
    if (i < n) {
        int o = sprefix + incl - v;
        g_off[i] = o;
        g_cur[i] = o;
    }
}

// ---------------------------------------------------------------------------
// 3) scatter edges into CSR order (atomic cursor), 2 edges/thread
// ---------------------------------------------------------------------------
__global__ void __launch_bounds__(256) scatter_kernel(
    const void* __restrict__ ei, const void* __restrict__ et, int E)
{
    int base = (blockIdx.x * 256 + threadIdx.x) * 2;
    if (base >= E) return;
    int m = E - base; if (m > 2) m = 2;
    int head[2], pk[2];
    if (detect64(et)) {
        const long long* pe = (const long long*)ei;
        const long long* pt = (const long long*)et;
        for (int i = 0; i < m; i++) {
            head[i] = (int)pe[base + i];
            int tail = (int)pe[(size_t)E + base + i];
            int rel  = (int)pt[base + i] - 2;
            pk[i] = tail | (rel << 20);
        }
    } else {
        const int* pe = (const int*)ei;
        const int* pt = (const int*)et;
        for (int i = 0; i < m; i++) {
            head[i] = pe[base + i];
            int tail = pe[(size_t)E + base + i];
            int rel  = pt[base + i] - 2;
            pk[i] = tail | (rel << 20);
        }
    }
    for (int i = 0; i < m; i++) {
        int pos = atomicAdd(&g_cur[head[i]], 1);
        g_packed[pos] = pk[i];
    }
}

// ---------------------------------------------------------------------------
// 4) segment mean: one warp per head, lane owns channels [2l,2l+2) packed
// f32x2. Packed indices batch-loaded 32-at-a-time and shfl-distributed;
// dual accumulators for MLP. Coalesced 256B row gathers (L2-resident).
// ---------------------------------------------------------------------------
__global__ void __launch_bounds__(256) seg_kernel(
    const float* __restrict__ entity_emb, const float* __restrict__ weight,
    float* __restrict__ ent_out, int n_ent)
{
    int head = (blockIdx.x * 256 + threadIdx.x) >> 5;
    if (head >= n_ent) return;
    int lane = threadIdx.x & 31;

    int start = g_off[head];
    int n     = g_hist[head];

    const unsigned long long* ent8 = (const unsigned long long*)entity_emb;
    const unsigned long long* w8   = (const unsigned long long*)weight;

    unsigned long long acc0 = 0ull, acc1 = 0ull;
    for (int base = 0; base < n; base += 32) {
        int m = n - base; if (m > 32) m = 32;
        int p = 0;
        if (lane < m) p = g_packed[start + base + lane];
        int i = 0;
        for (; i + 2 <= m; i += 2) {
            int p0 = __shfl_sync(~0u, p, i);
            int p1 = __shfl_sync(~0u, p, i + 1);
            unsigned long long e0 = ent8[(size_t)(p0 & 0xFFFFF) * 32 + lane];
            unsigned long long w0 = w8[(size_t)(p0 >> 20) * 32 + lane];
            unsigned long long e1 = ent8[(size_t)(p1 & 0xFFFFF) * 32 + lane];
            unsigned long long w1 = w8[(size_t)(p1 >> 20) * 32 + lane];
            asm("fma.rn.f32x2 %0, %1, %2, %0;" : "+l"(acc0) : "l"(e0), "l"(w0));
            asm("fma.rn.f32x2 %0, %1, %2, %0;" : "+l"(acc1) : "l"(e1), "l"(w1));
        }
        if (i < m) {
            int p0 = __shfl_sync(~0u, p, i);
            unsigned long long e0 = ent8[(size_t)(p0 & 0xFFFFF) * 32 + lane];
            unsigned long long w0 = w8[(size_t)(p0 >> 20) * 32 + lane];
            asm("fma.rn.f32x2 %0, %1, %2, %0;" : "+l"(acc0) : "l"(e0), "l"(w0));
        }
    }
    asm("add.rn.f32x2 %0, %0, %1;" : "+l"(acc0) : "l"(acc1));

    float inv = 1.0f / (float)max(n, 1);
    float2 a;
    asm("mov.b64 {%0, %1}, %2;" : "=f"(a.x), "=f"(a.y) : "l"(acc0));
    a.x *= inv; a.y *= inv;
    ((float2*)(ent_out + (size_t)head * CH))[lane] = a;
}

// ---------------------------------------------------------------------------
// Fused GEMMs: out = 2*(mat @ A) (softmax row-sum == 1 collapses the score
// term to a factor of 2). 512 rows/block, 512 threads; thread (g,q) computes
// rows {g+64i} x cols [8q,8q+8) with packed fma.rn.f32x2.
// ---------------------------------------------------------------------------
__global__ void __launch_bounds__(512, 1) gemm_fused_kernel(
    const float* __restrict__ ia, int n_items,
    const float* __restrict__ ua, int n_users,
    const float* __restrict__ A,
    float* __restrict__ item_out, float* __restrict__ user_out,
    int item_blocks)
{
    extern __shared__ float sm[];
    float*  sA  = sm;                       // 64x64, permuted
    float4* sM4 = (float4*)(sm + 4096);     // 512 rows x 17 float4

    const float* mat; float* out; int nrows; int row0;
    if ((int)blockIdx.x < item_blocks) {
        mat = ia; out = item_out; nrows = n_items; row0 = blockIdx.x * GR;
    } else {
        mat = ua; out = user_out; nrows = n_users;
        row0 = (blockIdx.x - item_blocks) * GR;
    }

    int tid = threadIdx.x;

    const float4* A4 = (const float4*)A;
    float4* sA4 = (float4*)sA;
    for (int idx = tid; idx < 1024; idx += 512) {
        int k = idx >> 4, c = idx & 15;
        sA4[k * 16 + ((c & 1) << 3) + (c >> 1)] = A4[idx];
    }
    const float4* mat4 = (const float4*)mat;
    for (int idx = tid; idx < GR * 16; idx += 512) {
        int r = idx >> 4, c = idx & 15;
        int gr = row0 + r;
        float4 v = make_float4(0.f, 0.f, 0.f, 0.f);
        if (gr < nrows) v = mat4[(size_t)gr * 16 + c];
        sM4[r * 17 + c] = v;
    }
    __syncthreads();

    int g = tid >> 3, q = tid & 7;
    unsigned long long acc[8][4];
    #pragma unroll
    for (int i = 0; i < 8; i++)
        #pragma unroll
        for (int p = 0; p < 4; p++) acc[i][p] = 0ull;

    const ulonglong2* sA8 = (const ulonglong2*)sA;

    for (int kk = 0; kk < 16; kk++) {
        float4 mv[8];
        #pragma unroll
        for (int i = 0; i < 8; i++) mv[i] = sM4[(g + 64 * i) * 17 + kk];

        #pragma unroll
        for (int u = 0; u < 4; u++) {
            int k = kk * 4 + u;
            ulonglong2 b0 = sA8[k * 16 + q];
            ulonglong2 b1 = sA8[k * 16 + 8 + q];
            #pragma unroll
            for (int i = 0; i < 8; i++) {
                float mu = (u == 0) ? mv[i].x : (u == 1) ? mv[i].y
                         : (u == 2) ? mv[i].z : mv[i].w;
                unsigned long long m2;
                asm("mov.b64 %0, {%1, %1};" : "=l"(m2) : "f"(mu));
                asm("fma.rn.f32x2 %0, %1, %2, %0;" : "+l"(acc[i][0]) : "l"(b0.x), "l"(m2));
                asm("fma.rn.f32x2 %0, %1, %2, %0;" : "+l"(acc[i][1]) : "l"(b0.y), "l"(m2));
                asm("fma.rn.f32x2 %0, %1, %2, %0;" : "+l"(acc[i][2]) : "l"(b1.x), "l"(m2));
                asm("fma.rn.f32x2 %0, %1, %2, %0;" : "+l"(acc[i][3]) : "l"(b1.y), "l"(m2));
            }
        }
    }

    #pragma unroll
    for (int i = 0; i < 8; i++) {
        int gr = row0 + g + 64 * i;
        if (gr < nrows) {
            ulonglong2* o = (ulonglong2*)(out + (size_t)gr * CH + q * 8);
            unsigned long long d0, d1, d2, d3;
            asm("add.rn.f32x2 %0, %1, %1;" : "=l"(d0) : "l"(acc[i][0]));
            asm("add.rn.f32x2 %0, %1, %1;" : "=l"(d1) : "l"(acc[i][1]));
            asm("add.rn.f32x2 %0, %1, %1;" : "=l"(d2) : "l"(acc[i][2]));
            asm("add.rn.f32x2 %0, %1, %1;" : "=l"(d3) : "l"(acc[i][3]));
            ulonglong2 w0; w0.x = d0; w0.y = d1;
            ulonglong2 w1; w1.x = d2; w1.y = d3;
            o[0] = w0; o[1] = w1;
        }
    }
}

// ---------------------------------------------------------------------------
// Launch. Edge pipeline on the capture stream; GEMM forked onto a side
// stream AFTER the scan so it overlaps only scatter+seg (L2/LSU-bound),
// leaving the latency-critical front stages (hist, scan) unimpeded.
// Streams/events are host objects (no device allocation), capture-legal.
// ---------------------------------------------------------------------------
extern "C" void kernel_launch(void* const* d_in, const int* in_sizes, int n_in,
                              void* d_out, int out_size)
{
    const float* entity_emb = (const float*)d_in[0];
    const float* aspect_emb = (const float*)d_in[3];
    const void*  edge_index = d_in[4];
    const void*  edge_type  = d_in[5];
    const float* ua_mat     = (const float*)d_in[6];
    const float* ia_mat     = (const float*)d_in[7];
    const float* weight     = (const float*)d_in[8];

    int n_ent   = in_sizes[0] / CH;
    int n_users = in_sizes[6] / CH;
    int n_items = in_sizes[7] / CH;
    int E       = in_sizes[5];

    float* out      = (float*)d_out;
    float* item_out = out;
    float* ent_out  = out + (size_t)n_items * CH;
    float* user_out = ent_out + (size_t)n_ent * CH;

    cudaStream_t s2 = 0;
    cudaEvent_t evMid = 0, evJoin = 0;
    bool forked = (cudaStreamCreateWithFlags(&s2, cudaStreamNonBlocking) == cudaSuccess)
               && (cudaEventCreateWithFlags(&evMid, cudaEventDisableTiming) == cudaSuccess)
               && (cudaEventCreateWithFlags(&evJoin, cudaEventDisableTiming) == cudaSuccess);

    // --- edge pipeline front (default stream) ---
    void* hist_ptr = nullptr;
    cudaGetSymbolAddress(&hist_ptr, g_hist);
    cudaMemsetAsync(hist_ptr, 0, (size_t)n_ent * sizeof(int));

    hist_kernel<<<(E + 1023) / 1024, 256>>>(edge_index, edge_type, E);
    int ntiles = (n_ent + STILE - 1) / STILE;
    scan_kernel<<<ntiles, STILE>>>(n_ent);

    // --- fork GEMM here: overlaps scatter + seg ---
    if (forked) {
        cudaEventRecord(evMid, 0);
        cudaStreamWaitEvent(s2, evMid, 0);
    }
    {
        int item_blocks = (n_items + GR - 1) / GR;
        int user_blocks = (n_users + GR - 1) / GR;
        int smem_bytes  = (4096 + GR * 68) * sizeof(float);   // 152 KB
        cudaFuncSetAttribute(gemm_fused_kernel,
                             cudaFuncAttributeMaxDynamicSharedMemorySize,
                             smem_bytes);
        gemm_fused_kernel<<<item_blocks + user_blocks, 512, smem_bytes,
                            forked ? s2 : 0>>>(
            ia_mat, n_items, ua_mat, n_users, aspect_emb,
            item_out, user_out, item_blocks);
    }

    // --- edge pipeline back (default stream) ---
    scatter_kernel<<<(E + 511) / 512, 256>>>(edge_index, edge_type, E);
    seg_kernel<<<(n_ent * 32 + 255) / 256, 256>>>(entity_emb, weight,
                                                  ent_out, n_ent);

    // --- join ---
    if (forked) {
        cudaEventRecord(evJoin, s2);
        cudaStreamWaitEvent(0, evJoin, 0);
        cudaStreamDestroy(s2);
        cudaEventDestroy(evMid);
        cudaEventDestroy(evJoin);
    }
}

// round 15
// speedup vs baseline: 1.2151x; 1.0492x over previous
#include <cuda_runtime.h>
#include <cstdint>
#include <cstddef>

#define CH 64
#define ENT_MAX 100000
#define E_MAX   1250000
#define GR 512            // rows per gemm block
#define STILE 1024        // scan tile

__device__ int g_hist[ENT_MAX];          // per-head edge count
__device__ int g_off[ENT_MAX];           // exclusive CSR offsets
__device__ int g_rank[E_MAX];            // per-edge rank within its head
__device__ int g_packed[E_MAX];          // tail | rel<<20, grouped by head
__device__ long long g_desc[128];        // scan tile descriptors

// is64 detection from edge_type[0] (values in [2,18); an 8B read of an int32
// buffer is >= 2^32, never in [2,64)).
__device__ __forceinline__ bool detect64(const void* et) {
    long long v = ((const long long*)et)[0];
    return (v >= 2 && v < 64);
}

// ---------------------------------------------------------------------------
// 1) histogram of heads + per-edge rank (atomicAdd return value), 4 edges/
// thread with vector loads. Block 0 zeroes the scan descriptors (consumed
// only by the NEXT launch -> launch boundary orders it).
// ---------------------------------------------------------------------------
__global__ void __launch_bounds__(256) hist_kernel(
    const void* __restrict__ ei, const void* __restrict__ et, int E)
{
    if (blockIdx.x == 0 && threadIdx.x < 128) g_desc[threadIdx.x] = 0;

    int base = (blockIdx.x * 256 + threadIdx.x) * 4;
    if (base >= E) return;
    int h[4];
    int m = E - base; if (m > 4) m = 4;
    if (detect64(et)) {
        const longlong2* p = (const longlong2*)((const long long*)ei + base);
        if (m == 4) {
            longlong2 a = p[0], b = p[1];
            h[0] = (int)a.x; h[1] = (int)a.y; h[2] = (int)b.x; h[3] = (int)b.y;
        } else {
            for (int i = 0; i < m; i++) h[i] = (int)((const long long*)ei)[base + i];
        }
    } else {
        if (m == 4) {
            int4 a = *(const int4*)((const int*)ei + base);
            h[0] = a.x; h[1] = a.y; h[2] = a.z; h[3] = a.w;
        } else {
            for (int i = 0; i < m; i++) h[i] = ((const int*)ei)[base + i];
        }
    }
    for (int i = 0; i < m; i++)
        g_rank[base + i] = atomicAdd(&g_hist[h[i]], 1);
}

// ---------------------------------------------------------------------------
// 2) single-kernel exclusive scan of g_hist -> g_off.
// Tile-local scan, publish (total<<32)|1, warp 0 lookback-sums earlier tiles.
// Safe under partial residency: tile k waits only on earlier-bid tiles,
// which are scheduled first and complete without waiting on later tiles.
// ---------------------------------------------------------------------------
__global__ void __launch_bounds__(STILE) scan_kernel(int n)
{
    __shared__ int wsum[32];
    __shared__ int sprefix;
    int tile = blockIdx.x, t = threadIdx.x, lane = t & 31, w = t >> 5;
    int i = tile * STILE + t;
    int v = (i < n) ? g_hist[i] : 0;
    int x = v;
    #pragma unroll
    for (int o = 1; o < 32; o <<= 1) {
        int y = __shfl_up_sync(~0u, x, o);
        if (lane >= o) x += y;
    }
    if (lane == 31) wsum[w] = x;
    __syncthreads();
    if (w == 0) {
        int y = wsum[lane];
        #pragma unroll
        for (int o = 1; o < 32; o <<= 1) {
            int z = __shfl_up_sync(~0u, y, o);
            if (lane >= o) y += z;
        }
        wsum[lane] = y;
    }
    __syncthreads();
    int incl  = x + (w ? wsum[w - 1] : 0);
    int total = wsum[31];
    if (t == 0) {
        __threadfence();
        ((volatile long long*)g_desc)[tile] = ((long long)total << 32) | 1ll;
    }
    if (w == 0) {
        int sum = 0;
        for (int base = 0; base < tile; base += 32) {
            int idx = base + lane;
            int a = 0;
            if (idx < tile) {
                long long d;
                do { d = ((volatile long long*)g_desc)[idx]; } while (d == 0);
                a = (int)(d >> 32);
            }
            #pragma unroll
            for (int o = 16; o >= 1; o >>= 1) a += __shfl_down_sync(~0u, a, o);
            if (lane == 0) sum += a;
        }
        if (lane == 0) sprefix = sum;
    }
    __syncthreads();
    if (i < n) g_off[i] = sprefix + incl - v;
}

// ---------------------------------------------------------------------------
// 3) ATOMIC-FREE scatter into CSR order via precomputed ranks, 2 edges/thr.
// ---------------------------------------------------------------------------
__global__ void __launch_bounds__(256) scatter_kernel(
    const void* __restrict__ ei, const void* __restrict__ et, int E)
{
    int base = (blockIdx.x * 256 + threadIdx.x) * 2;
    if (base >= E) return;
    int m = E - base; if (m > 2) m = 2;
    int head[2], pk[2];
    if (detect64(et)) {
        const long long* pe = (const long long*)ei;
        const long long* pt = (const long long*)et;
        for (int i = 0; i < m; i++) {
            head[i] = (int)pe[base + i];
            int tail = (int)pe[(size_t)E + base + i];
            int rel  = (int)pt[base + i] - 2;
            pk[i] = tail | (rel << 20);
        }
    } else {
        const int* pe = (const int*)ei;
        const int* pt = (const int*)et;
        for (int i = 0; i < m; i++) {
            head[i] = pe[base + i];
            int tail = pe[(size_t)E + base + i];
            int rel  = pt[base + i] - 2;
            pk[i] = tail | (rel << 20);
        }
    }
    for (int i = 0; i < m; i++)
        g_packed[g_off[head[i]] + g_rank[base + i]] = pk[i];
}

// ---------------------------------------------------------------------------
// 4) segment mean: one warp per head, lane owns channels [2l,2l+2) packed
// f32x2. Packed indices batch-loaded 32-at-a-time and shfl-distributed;
// dual accumulators for MLP. Coalesced 256B row gathers (L2-resident).
// ---------------------------------------------------------------------------
__global__ void __launch_bounds__(256) seg_kernel(
    const float* __restrict__ entity_emb, const float* __restrict__ weight,
    float* __restrict__ ent_out, int n_ent)
{
    int head = (blockIdx.x * 256 + threadIdx.x) >> 5;
    if (head >= n_ent) return;
    int lane = threadIdx.x & 31;

    int start = g_off[head];
    int n     = g_hist[head];

    const unsigned long long* ent8 = (const unsigned long long*)entity_emb;
    const unsigned long long* w8   = (const unsigned long long*)weight;

    unsigned long long acc0 = 0ull, acc1 = 0ull;
    for (int base = 0; base < n; base += 32) {
        int m = n - base; if (m > 32) m = 32;
        int p = 0;
        if (lane < m) p = g_packed[start + base + lane];
        int i = 0;
        for (; i + 2 <= m; i += 2) {
            int p0 = __shfl_sync(~0u, p, i);
            int p1 = __shfl_sync(~0u, p, i + 1);
            unsigned long long e0 = ent8[(size_t)(p0 & 0xFFFFF) * 32 + lane];
            unsigned long long w0 = w8[(size_t)(p0 >> 20) * 32 + lane];
            unsigned long long e1 = ent8[(size_t)(p1 & 0xFFFFF) * 32 + lane];
            unsigned long long w1 = w8[(size_t)(p1 >> 20) * 32 + lane];
            asm("fma.rn.f32x2 %0, %1, %2, %0;" : "+l"(acc0) : "l"(e0), "l"(w0));
            asm("fma.rn.f32x2 %0, %1, %2, %0;" : "+l"(acc1) : "l"(e1), "l"(w1));
        }
        if (i < m) {
            int p0 = __shfl_sync(~0u, p, i);
            unsigned long long e0 = ent8[(size_t)(p0 & 0xFFFFF) * 32 + lane];
            unsigned long long w0 = w8[(size_t)(p0 >> 20) * 32 + lane];
            asm("fma.rn.f32x2 %0, %1, %2, %0;" : "+l"(acc0) : "l"(e0), "l"(w0));
        }
    }
    asm("add.rn.f32x2 %0, %0, %1;" : "+l"(acc0) : "l"(acc1));

    float inv = 1.0f / (float)max(n, 1);
    float2 a;
    asm("mov.b64 {%0, %1}, %2;" : "=f"(a.x), "=f"(a.y) : "l"(acc0));
    a.x *= inv; a.y *= inv;
    ((float2*)(ent_out + (size_t)head * CH))[lane] = a;
}

// ---------------------------------------------------------------------------
// Fused GEMMs: out = 2*(mat @ A) (softmax row-sum == 1 collapses the score
// term to a factor of 2). 512 rows/block, 512 threads; thread (g,q) computes
// rows {g+64i} x cols [8q,8q+8) with packed fma.rn.f32x2.
// ---------------------------------------------------------------------------
__global__ void __launch_bounds__(512, 1) gemm_fused_kernel(
    const float* __restrict__ ia, int n_items,
    const float* __restrict__ ua, int n_users,
    const float* __restrict__ A,
    float* __restrict__ item_out, float* __restrict__ user_out,
    int item_blocks)
{
    extern __shared__ float sm[];
    float*  sA  = sm;                       // 64x64, permuted
    float4* sM4 = (float4*)(sm + 4096);     // 512 rows x 17 float4

    const float* mat; float* out; int nrows; int row0;
    if ((int)blockIdx.x < item_blocks) {
        mat = ia; out = item_out; nrows = n_items; row0 = blockIdx.x * GR;
    } else {
        mat = ua; out = user_out; nrows = n_users;
        row0 = (blockIdx.x - item_blocks) * GR;
    }

    int tid = threadIdx.x;

    const float4* A4 = (const float4*)A;
    float4* sA4 = (float4*)sA;
    for (int idx = tid; idx < 1024; idx += 512) {
        int k = idx >> 4, c = idx & 15;
        sA4[k * 16 + ((c & 1) << 3) + (c >> 1)] = A4[idx];
    }
    const float4* mat4 = (const float4*)mat;
    for (int idx = tid; idx < GR * 16; idx += 512) {
        int r = idx >> 4, c = idx & 15;
        int gr = row0 + r;
        float4 v = make_float4(0.f, 0.f, 0.f, 0.f);
        if (gr < nrows) v = mat4[(size_t)gr * 16 + c];
        sM4[r * 17 + c] = v;
    }
    __syncthreads();

    int g = tid >> 3, q = tid & 7;
    unsigned long long acc[8][4];
    #pragma unroll
    for (int i = 0; i < 8; i++)
        #pragma unroll
        for (int p = 0; p < 4; p++) acc[i][p] = 0ull;

    const ulonglong2* sA8 = (const ulonglong2*)sA;

    for (int kk = 0; kk < 16; kk++) {
        float4 mv[8];
        #pragma unroll
        for (int i = 0; i < 8; i++) mv[i] = sM4[(g + 64 * i) * 17 + kk];

        #pragma unroll
        for (int u = 0; u < 4; u++) {
            int k = kk * 4 + u;
            ulonglong2 b0 = sA8[k * 16 + q];
            ulonglong2 b1 = sA8[k * 16 + 8 + q];
            #pragma unroll
            for (int i = 0; i < 8; i++) {
                float mu = (u == 0) ? mv[i].x : (u == 1) ? mv[i].y
                         : (u == 2) ? mv[i].z : mv[i].w;
                unsigned long long m2;
                asm("mov.b64 %0, {%1, %1};" : "=l"(m2) : "f"(mu));
                asm("fma.rn.f32x2 %0, %1, %2, %0;" : "+l"(acc[i][0]) : "l"(b0.x), "l"(m2));
                asm("fma.rn.f32x2 %0, %1, %2, %0;" : "+l"(acc[i][1]) : "l"(b0.y), "l"(m2));
                asm("fma.rn.f32x2 %0, %1, %2, %0;" : "+l"(acc[i][2]) : "l"(b1.x), "l"(m2));
                asm("fma.rn.f32x2 %0, %1, %2, %0;" : "+l"(acc[i][3]) : "l"(b1.y), "l"(m2));
            }
        }
    }

    #pragma unroll
    for (int i = 0; i < 8; i++) {
        int gr = row0 + g + 64 * i;
        if (gr < nrows) {
            ulonglong2* o = (ulonglong2*)(out + (size_t)gr * CH + q * 8);
            unsigned long long d0, d1, d2, d3;
            asm("add.rn.f32x2 %0, %1, %1;" : "=l"(d0) : "l"(acc[i][0]));
            asm("add.rn.f32x2 %0, %1, %1;" : "=l"(d1) : "l"(acc[i][1]));
            asm("add.rn.f32x2 %0, %1, %1;" : "=l"(d2) : "l"(acc[i][2]));
            asm("add.rn.f32x2 %0, %1, %1;" : "=l"(d3) : "l"(acc[i][3]));
            ulonglong2 w0; w0.x = d0; w0.y = d1;
            ulonglong2 w1; w1.x = d2; w1.y = d3;
            o[0] = w0; o[1] = w1;
        }
    }
}

// ---------------------------------------------------------------------------
// Launch. GEMM forked at t=0 (empirically best overlap); edge pipeline
// memset -> hist -> scan -> scatter -> seg on the capture stream.
// Streams/events are host objects (no device allocation), capture-legal.
// ---------------------------------------------------------------------------
extern "C" void kernel_launch(void* const* d_in, const int* in_sizes, int n_in,
                              void* d_out, int out_size)
{
    const float* entity_emb = (const float*)d_in[0];
    const float* aspect_emb = (const float*)d_in[3];
    const void*  edge_index = d_in[4];
    const void*  edge_type  = d_in[5];
    const float* ua_mat     = (const float*)d_in[6];
    const float* ia_mat     = (const float*)d_in[7];
    const float* weight     = (const float*)d_in[8];

    int n_ent   = in_sizes[0] / CH;
    int n_users = in_sizes[6] / CH;
    int n_items = in_sizes[7] / CH;
    int E       = in_sizes[5];

    float* out      = (float*)d_out;
    float* item_out = out;
    float* ent_out  = out + (size_t)n_items * CH;
    float* user_out = ent_out + (size_t)n_ent * CH;

    cudaStream_t s2 = 0;
    cudaEvent_t evFork = 0, evJoin = 0;
    bool forked = (cudaStreamCreateWithFlags(&s2, cudaStreamNonBlocking) == cudaSuccess)
               && (cudaEventCreateWithFlags(&evFork, cudaEventDisableTiming) == cudaSuccess)
               && (cudaEventCreateWithFlags(&evJoin, cudaEventDisableTiming) == cudaSuccess);
    if (forked) {
        cudaEventRecord(evFork, 0);
        cudaStreamWaitEvent(s2, evFork, 0);
    }

    // --- GEMM branch (side stream) ---
    {
        int item_blocks = (n_items + GR - 1) / GR;
        int user_blocks = (n_users + GR - 1) / GR;
        int smem_bytes  = (4096 + GR * 68) * sizeof(float);   // 152 KB
        cudaFuncSetAttribute(gemm_fused_kernel,
                             cudaFuncAttributeMaxDynamicSharedMemorySize,
                             smem_bytes);
        gemm_fused_kernel<<<item_blocks + user_blocks, 512, smem_bytes,
                            forked ? s2 : 0>>>(
            ia_mat, n_items, ua_mat, n_users, aspect_emb,
            item_out, user_out, item_blocks);
    }

    // --- edge pipeline (default stream) ---
    void* hist_ptr = nullptr;
    cudaGetSymbolAddress(&hist_ptr, g_hist);
    cudaMemsetAsync(hist_ptr, 0, (size_t)n_ent * sizeof(int));

    hist_kernel<<<(E + 1023) / 1024, 256>>>(edge_index, edge_type, E);
    int ntiles = (n_ent + STILE - 1) / STILE;
    scan_kernel<<<ntiles, STILE>>>(n_ent);
    scatter_kernel<<<(E + 511) / 512, 256>>>(edge_index, edge_type, E);
    seg_kernel<<<(n_ent * 32 + 255) / 256, 256>>>(entity_emb, weight,
                                                  ent_out, n_ent);

    // --- join ---
    if (forked) {
        cudaEventRecord(evJoin, s2);
        cudaStreamWaitEvent(0, evJoin, 0);
        cudaStreamDestroy(s2);
        cudaEventDestroy(evFork);
        cudaEventDestroy(evJoin);
    }
}